// round 1
// baseline (speedup 1.0000x reference)
#include <cuda_runtime.h>

// TranVectorQuantizer: latent [32768, 8, 32] f32, codebook [128, 32] f32
// Outputs (concatenated in d_out, f32):
//   policy    [32768, 8, 32]    = latent + (quantized - latent)   (8388608)
//   quantized [32768, 8, 32]    = codebook[argmin dist]           (8388608)
//   codebook_set [32768,128,32] = broadcast codebook              (134217728)

#define KCODES 128
#define DDIM 32

__global__ __launch_bounds__(256, 3) void vq_kernel(
    const float* __restrict__ latent,
    const float* __restrict__ codebook,
    float* __restrict__ out_policy,
    float* __restrict__ out_quant,
    float* __restrict__ out_cbset,
    int nChunks)  // number of 32-batch-element chunks
{
    __shared__ float cb[KCODES * DDIM];  // 16 KB
    __shared__ float cn[KCODES];         // code norms

    const int t = threadIdx.x;

    // --- stage codebook into smem (1024 float4, 4 per thread) ---
    {
        const float4* src = (const float4*)codebook;
        float4* dst = (float4*)cb;
#pragma unroll
        for (int j = 0; j < 4; j++) dst[t + j * 256] = src[t + j * 256];
    }
    __syncthreads();

    // --- code norms: sequential fma chain matching jnp.sum(cb**2, -1) ---
    if (t < KCODES) {
        float s = 0.f;
#pragma unroll
        for (int i = 0; i < DDIM; i++) {
            float c = cb[t * DDIM + i];
            s = fmaf(c, c, s);
        }
        cn[t] = s;
    }

    // --- preload this thread's replication payload into registers ---
    float4 creg[4];
    {
        const float4* cbv = (const float4*)cb;
#pragma unroll
        for (int j = 0; j < 4; j++) creg[j] = cbv[t + j * 256];
    }
    __syncthreads();

    const float4* cb4 = (const float4*)cb;

    for (int chunk = blockIdx.x; chunk < nChunks; chunk += gridDim.x) {
        const long long n = (long long)chunk * 256 + t;  // vector index

        // load this thread's vector (one full 128B line)
        float x[DDIM];
        {
            const float4* lp = (const float4*)(latent + n * DDIM);
#pragma unroll
            for (int j = 0; j < 8; j++) {
                float4 v = lp[j];
                x[4 * j + 0] = v.x; x[4 * j + 1] = v.y;
                x[4 * j + 2] = v.z; x[4 * j + 3] = v.w;
            }
        }

        // ||x||^2 — sequential fma chain (matches reference reduce order)
        float xx = 0.f;
#pragma unroll
        for (int i = 0; i < DDIM; i++) xx = fmaf(x[i], x[i], xx);

        // argmin over 128 codes: d = (xx + cc[k]) - 2*dot  (reference formula)
        float best = __int_as_float(0x7f800000);  // +inf
        int bk = 0;
#pragma unroll 4
        for (int k = 0; k < KCODES; k++) {
            float dot = 0.f;
#pragma unroll
            for (int j = 0; j < 8; j++) {
                float4 c = cb4[k * 8 + j];  // broadcast across the warp
                dot = fmaf(x[4 * j + 0], c.x, dot);
                dot = fmaf(x[4 * j + 1], c.y, dot);
                dot = fmaf(x[4 * j + 2], c.z, dot);
                dot = fmaf(x[4 * j + 3], c.w, dot);
            }
            float d = (xx + cn[k]) - 2.0f * dot;
            if (d < best) { best = d; bk = k; }  // strict < keeps first index on ties
        }

        // write quantized + policy (policy = x + (q - x), elementwise fp32)
        {
            float4* qo = (float4*)(out_quant + n * DDIM);
            float4* po = (float4*)(out_policy + n * DDIM);
            const float4* cq = (const float4*)(cb + bk * DDIM);
#pragma unroll
            for (int j = 0; j < 8; j++) {
                float4 q = cq[j];
                float4 p;
                p.x = x[4 * j + 0] + (q.x - x[4 * j + 0]);
                p.y = x[4 * j + 1] + (q.y - x[4 * j + 1]);
                p.z = x[4 * j + 2] + (q.z - x[4 * j + 2]);
                p.w = x[4 * j + 3] + (q.w - x[4 * j + 3]);
                qo[j] = q;
                po[j] = p;
            }
        }

        // codebook_set replication: 32 batch elems * 16KB, from registers
        const long long bbase = (long long)chunk * 32;
#pragma unroll 4
        for (int b = 0; b < 32; b++) {
            float4* o = (float4*)(out_cbset + (bbase + b) * (KCODES * DDIM));
#pragma unroll
            for (int j = 0; j < 4; j++) o[t + j * 256] = creg[j];
        }
    }
}

extern "C" void kernel_launch(void* const* d_in, const int* in_sizes, int n_in,
                              void* d_out, int out_size) {
    const float* latent = (const float*)d_in[0];
    const float* codebook = (const float*)d_in[1];

    const long long Nvec = (long long)in_sizes[0] / DDIM;   // 262144
    const long long B = Nvec / 8;                           // 32768
    const int nChunks = (int)(B / 32);                      // 1024

    float* out_policy = (float*)d_out;
    float* out_quant = out_policy + Nvec * DDIM;
    float* out_cbset = out_quant + Nvec * DDIM;

    vq_kernel<<<nChunks, 256>>>(latent, codebook, out_policy, out_quant,
                                out_cbset, nChunks);
}

// round 2
// speedup vs baseline: 1.0211x; 1.0211x over previous
#include <cuda_runtime.h>

// TranVectorQuantizer: latent [32768, 8, 32] f32, codebook [128, 32] f32
// Outputs (concatenated in d_out, f32):
//   policy    [32768, 8, 32]    = latent + (quantized - latent)   (8388608)
//   quantized [32768, 8, 32]    = codebook[argmin dist]           (8388608)
//   codebook_set [32768,128,32] = broadcast codebook              (134217728)
//
// Grid role split: blocks [0, NSTORE) stream the codebook_set broadcast
// (84% of DRAM traffic, zero compute); blocks [NSTORE, NSTORE+NCOMP) do the
// argmin + policy/quant. Co-resident mixed CTAs per SM overlap the
// latency-bound fma chains with the bandwidth-bound store stream.

#define KCODES 128
#define DDIM 32
#define NSTORE 128              // store blocks; 32768/128 = 256 batch elems each
#define NCOMP  328              // compute blocks (total 456 = 152 SMs * 3 CTAs)

__global__ __launch_bounds__(256, 3) void vq_kernel(
    const float* __restrict__ latent,
    const float* __restrict__ codebook,
    float* __restrict__ out_policy,
    float* __restrict__ out_quant,
    float* __restrict__ out_cbset,
    int nChunks, int nBatch)
{
    const int t = threadIdx.x;
    const int bid = blockIdx.x;

    if (bid < NSTORE) {
        // ─── STORE ROLE: pure codebook_set replication ───────────────────
        // 16 KB codebook lives in 16 registers/thread; stream 256 copies.
        float4 creg[4];
        const float4* src = (const float4*)codebook;
#pragma unroll
        for (int j = 0; j < 4; j++) creg[j] = __ldg(&src[t + j * 256]);

        const int per = nBatch / NSTORE;             // 256
        float4* base = (float4*)out_cbset + (long long)bid * per * 1024 + t;
#pragma unroll 4
        for (int i = 0; i < per; i++) {
            float4* o = base + (long long)i * 1024;
            __stcs(o,        creg[0]);
            __stcs(o + 256,  creg[1]);
            __stcs(o + 512,  creg[2]);
            __stcs(o + 768,  creg[3]);
        }
        return;
    }

    // ─── COMPUTE ROLE: argmin + policy/quant ─────────────────────────────
    __shared__ float cb[KCODES * DDIM];  // 16 KB
    __shared__ float cn[KCODES];         // code norms

    {
        const float4* src = (const float4*)codebook;
        float4* dst = (float4*)cb;
#pragma unroll
        for (int j = 0; j < 4; j++) dst[t + j * 256] = src[t + j * 256];
    }
    __syncthreads();

    if (t < KCODES) {
        float s = 0.f;
#pragma unroll
        for (int i = 0; i < DDIM; i++) {
            float c = cb[t * DDIM + i];
            s = fmaf(c, c, s);
        }
        cn[t] = s;
    }
    __syncthreads();

    const float4* cb4 = (const float4*)cb;

    for (int chunk = bid - NSTORE; chunk < nChunks; chunk += NCOMP) {
        const long long n = (long long)chunk * 256 + t;  // vector index

        // load this thread's vector (one full 128B line)
        float x[DDIM];
        {
            const float4* lp = (const float4*)(latent + n * DDIM);
#pragma unroll
            for (int j = 0; j < 8; j++) {
                float4 v = __ldcs(&lp[j]);
                x[4 * j + 0] = v.x; x[4 * j + 1] = v.y;
                x[4 * j + 2] = v.z; x[4 * j + 3] = v.w;
            }
        }

        // ||x||^2 — sequential fma chain (bit-matches reference argmin; DO NOT reorder)
        float xx = 0.f;
#pragma unroll
        for (int i = 0; i < DDIM; i++) xx = fmaf(x[i], x[i], xx);

        // argmin over 128 codes: d = (xx + cc[k]) - 2*dot
        float best = __int_as_float(0x7f800000);  // +inf
        int bk = 0;
#pragma unroll 4
        for (int k = 0; k < KCODES; k++) {
            float dot = 0.f;
#pragma unroll
            for (int j = 0; j < 8; j++) {
                float4 c = cb4[k * 8 + j];  // smem broadcast across the warp
                dot = fmaf(x[4 * j + 0], c.x, dot);
                dot = fmaf(x[4 * j + 1], c.y, dot);
                dot = fmaf(x[4 * j + 2], c.z, dot);
                dot = fmaf(x[4 * j + 3], c.w, dot);
            }
            float d = (xx + cn[k]) - 2.0f * dot;
            if (d < best) { best = d; bk = k; }  // strict < keeps first index on ties
        }

        // write quantized + policy (policy = x + (q - x), elementwise fp32)
        {
            float4* qo = (float4*)(out_quant + n * DDIM);
            float4* po = (float4*)(out_policy + n * DDIM);
            const float4* cq = (const float4*)(cb + bk * DDIM);
#pragma unroll
            for (int j = 0; j < 8; j++) {
                float4 q = cq[j];
                float4 p;
                p.x = x[4 * j + 0] + (q.x - x[4 * j + 0]);
                p.y = x[4 * j + 1] + (q.y - x[4 * j + 1]);
                p.z = x[4 * j + 2] + (q.z - x[4 * j + 2]);
                p.w = x[4 * j + 3] + (q.w - x[4 * j + 3]);
                __stcs(&qo[j], q);
                __stcs(&po[j], p);
            }
        }
    }
}

extern "C" void kernel_launch(void* const* d_in, const int* in_sizes, int n_in,
                              void* d_out, int out_size) {
    const float* latent = (const float*)d_in[0];
    const float* codebook = (const float*)d_in[1];

    const long long Nvec = (long long)in_sizes[0] / DDIM;   // 262144
    const int nBatch = (int)(Nvec / 8);                     // 32768
    const int nChunks = nBatch / 32;                        // 1024

    float* out_policy = (float*)d_out;
    float* out_quant = out_policy + Nvec * DDIM;
    float* out_cbset = out_quant + Nvec * DDIM;

    vq_kernel<<<NSTORE + NCOMP, 256>>>(latent, codebook, out_policy, out_quant,
                                       out_cbset, nChunks, nBatch);
}

// round 3
// speedup vs baseline: 1.0714x; 1.0493x over previous
#include <cuda_runtime.h>

// TranVectorQuantizer: latent [32768, 8, 32] f32, codebook [128, 32] f32
// Outputs (f32, concatenated in d_out):
//   policy    [32768, 8, 32]   = quantized (numerically x + (q - x))
//   quantized [32768, 8, 32]   = codebook[argmin dist]
//   codebook_set [32768,128,32]= broadcast codebook (512 MB, 84% of traffic)
//
// Role-split grid: NSTORE blocks stream the broadcast; NCOMP blocks do the
// argmin with f32x2-packed (FFMA2) distance chains — each packed lane is an
// independent fp32 FMA chain in the exact order that bit-matched XLA (rel_err 0).

#define KCODES 128
#define DDIM 32
#define NSTORE 104
#define NCOMP  200
#define NGRID  (NSTORE + NCOMP)

__device__ __forceinline__ float2 ffma2(float2 a, float2 b, float2 c) {
    float2 d;
    asm("fma.rn.f32x2 %0, %1, %2, %3;"
        : "=l"(reinterpret_cast<unsigned long long&>(d))
        : "l"(reinterpret_cast<unsigned long long&>(a)),
          "l"(reinterpret_cast<unsigned long long&>(b)),
          "l"(reinterpret_cast<unsigned long long&>(c)));
    return d;
}

__global__ __launch_bounds__(256, 2) void vq_kernel(
    const float* __restrict__ latent,
    const float* __restrict__ codebook,
    float* __restrict__ out_policy,
    float* __restrict__ out_quant,
    float* __restrict__ out_cbset,
    int nChunks, int nBatch)
{
    const int t = threadIdx.x;
    const int bid = blockIdx.x;

    if (bid < NSTORE) {
        // ─── STORE ROLE: codebook_set replication, pure STG.128 stream ───
        float4 creg[4];
        const float4* src = (const float4*)codebook;
#pragma unroll
        for (int j = 0; j < 4; j++) creg[j] = __ldg(&src[t + j * 256]);

        for (int b = bid; b < nBatch; b += NSTORE) {
            float4* o = (float4*)out_cbset + (long long)b * 1024 + t;
            __stcs(o,        creg[0]);
            __stcs(o + 256,  creg[1]);
            __stcs(o + 512,  creg[2]);
            __stcs(o + 768,  creg[3]);
        }
        return;
    }

    // ─── COMPUTE ROLE ────────────────────────────────────────────────────
    __shared__ float  cbs[KCODES * DDIM];        // raw codebook, 16 KB
    __shared__ float2 cbp[KCODES / 2][DDIM];     // k-pair interleaved, 16 KB
    __shared__ float  cn[KCODES];                // code norms

    {
        const float4* src = (const float4*)codebook;
        float4* dst = (float4*)cbs;
#pragma unroll
        for (int j = 0; j < 4; j++) dst[t + j * 256] = src[t + j * 256];
    }
    __syncthreads();

    // pack: cbp[p][i] = (cb[2p][i], cb[2p+1][i])
#pragma unroll
    for (int j = 0; j < 8; j++) {
        int q = t + j * 256;            // 0..2047
        int p = q >> 5, i = q & 31;
        cbp[p][i] = make_float2(cbs[(2 * p) * DDIM + i], cbs[(2 * p + 1) * DDIM + i]);
    }
    if (t < KCODES) {
        float s = 0.f;
#pragma unroll
        for (int i = 0; i < DDIM; i++) {
            float c = cbs[t * DDIM + i];
            s = fmaf(c, c, s);
        }
        cn[t] = s;
    }
    __syncthreads();

    for (int chunk = bid - NSTORE; chunk < nChunks; chunk += NCOMP) {
        const long long n = (long long)chunk * 256 + t;  // vector index

        // load vector; duplicate each component into a f32x2 pair
        float2 x2[DDIM];
        {
            const float4* lp = (const float4*)(latent + n * DDIM);
#pragma unroll
            for (int j = 0; j < 8; j++) {
                float4 v = __ldcs(&lp[j]);
                x2[4 * j + 0] = make_float2(v.x, v.x);
                x2[4 * j + 1] = make_float2(v.y, v.y);
                x2[4 * j + 2] = make_float2(v.z, v.z);
                x2[4 * j + 3] = make_float2(v.w, v.w);
            }
        }

        // ||x||^2 — sequential fma chain (bit-matches reference; DO NOT reorder)
        float xx = 0.f;
#pragma unroll
        for (int i = 0; i < DDIM; i++) xx = fmaf(x2[i].x, x2[i].x, xx);

        // argmin: 64 k-pairs, 2 pairs per iteration (4 codes), FFMA2 chains.
        // Each packed lane is a sequential i=0..31 fp32 fma chain -> bit-exact.
        float best = __int_as_float(0x7f800000);
        int bk = 0;
#pragma unroll 2
        for (int p = 0; p < KCODES / 2; p += 2) {
            float2 dotA = make_float2(0.f, 0.f);
            float2 dotB = make_float2(0.f, 0.f);
            const float4* ra = (const float4*)cbp[p];      // 16 x float4 (2 pairs each)
            const float4* rb = (const float4*)cbp[p + 1];
#pragma unroll
            for (int j = 0; j < 16; j++) {
                float4 a = ra[j];
                float4 b = rb[j];
                dotA = ffma2(x2[2 * j],     make_float2(a.x, a.y), dotA);
                dotA = ffma2(x2[2 * j + 1], make_float2(a.z, a.w), dotA);
                dotB = ffma2(x2[2 * j],     make_float2(b.x, b.y), dotB);
                dotB = ffma2(x2[2 * j + 1], make_float2(b.z, b.w), dotB);
            }
            float d0 = (xx + cn[2 * p + 0]) - 2.0f * dotA.x;
            float d1 = (xx + cn[2 * p + 1]) - 2.0f * dotA.y;
            float d2 = (xx + cn[2 * p + 2]) - 2.0f * dotB.x;
            float d3 = (xx + cn[2 * p + 3]) - 2.0f * dotB.y;
            if (d0 < best) { best = d0; bk = 2 * p + 0; }
            if (d1 < best) { best = d1; bk = 2 * p + 1; }
            if (d2 < best) { best = d2; bk = 2 * p + 2; }
            if (d3 < best) { best = d3; bk = 2 * p + 3; }
        }

        // write quantized + policy (policy = x + (q - x), elementwise fp32)
        {
            float4* qo = (float4*)(out_quant + n * DDIM);
            float4* po = (float4*)(out_policy + n * DDIM);
            const float4* cq = (const float4*)(cbs + bk * DDIM);
#pragma unroll
            for (int j = 0; j < 8; j++) {
                float4 q = cq[j];
                float4 p4;
                p4.x = x2[4 * j + 0].x + (q.x - x2[4 * j + 0].x);
                p4.y = x2[4 * j + 1].x + (q.y - x2[4 * j + 1].x);
                p4.z = x2[4 * j + 2].x + (q.z - x2[4 * j + 2].x);
                p4.w = x2[4 * j + 3].x + (q.w - x2[4 * j + 3].x);
                __stcs(&qo[j], q);
                __stcs(&po[j], p4);
            }
        }
    }
}

extern "C" void kernel_launch(void* const* d_in, const int* in_sizes, int n_in,
                              void* d_out, int out_size) {
    const float* latent = (const float*)d_in[0];
    const float* codebook = (const float*)d_in[1];

    const long long Nvec = (long long)in_sizes[0] / DDIM;   // 262144
    const int nBatch = (int)(Nvec / 8);                     // 32768
    const int nChunks = (int)(Nvec / 256);                  // 1024

    float* out_policy = (float*)d_out;
    float* out_quant = out_policy + Nvec * DDIM;
    float* out_cbset = out_quant + Nvec * DDIM;

    vq_kernel<<<NGRID, 256>>>(latent, codebook, out_policy, out_quant,
                              out_cbset, nChunks, nBatch);
}

// round 4
// speedup vs baseline: 1.2052x; 1.1249x over previous
#include <cuda_runtime.h>

// TranVectorQuantizer: latent [32768, 8, 32] f32, codebook [128, 32] f32
// Outputs (f32, concatenated):
//   policy    [32768, 8, 32]    (8388608)
//   quantized [32768, 8, 32]    (8388608)
//   codebook_set [32768,128,32] (134217728; 84% of DRAM traffic)
//
// Role-split grid (128-thread blocks): NSTORE blocks stream codebook_set;
// NCOMP blocks do argmin with V=2 register-blocked vectors per thread so each
// packed-codebook LDS feeds FFMA2 chains for two vectors (LDS/vector halved).
// Every per-vector chain keeps the exact sequential fp32 fma order that
// bit-matched XLA (rel_err 0.0).

#define KCODES 128
#define DDIM 32
#define NSTORE 200
#define NCOMP  256
#define NGRID  (NSTORE + NCOMP)

__device__ __forceinline__ float2 ffma2(float2 a, float2 b, float2 c) {
    float2 d;
    asm("fma.rn.f32x2 %0, %1, %2, %3;"
        : "=l"(reinterpret_cast<unsigned long long&>(d))
        : "l"(reinterpret_cast<unsigned long long&>(a)),
          "l"(reinterpret_cast<unsigned long long&>(b)),
          "l"(reinterpret_cast<unsigned long long&>(c)));
    return d;
}

__global__ void __launch_bounds__(128, 3) vq_kernel(
    const float* __restrict__ latent,
    const float* __restrict__ codebook,
    float* __restrict__ out_policy,
    float* __restrict__ out_quant,
    float* __restrict__ out_cbset,
    int nChunks, int nBatch)
{
    const int t = threadIdx.x;
    const int bid = blockIdx.x;

    if (bid < NSTORE) {
        // ─── STORE ROLE: codebook_set replication, pure STG.128 stream ───
        float4 creg[8];
        const float4* src = (const float4*)codebook;
#pragma unroll
        for (int j = 0; j < 8; j++) creg[j] = __ldg(&src[t + j * 128]);

        for (int b = bid; b < nBatch; b += NSTORE) {
            float4* o = (float4*)out_cbset + (long long)b * 1024 + t;
#pragma unroll
            for (int j = 0; j < 8; j++) __stcs(o + j * 128, creg[j]);
        }
        return;
    }

    // ─── COMPUTE ROLE ────────────────────────────────────────────────────
    __shared__ float  cbs[KCODES * DDIM];        // raw codebook, 16 KB
    __shared__ float2 cbp[KCODES / 2][DDIM];     // k-pair interleaved, 16 KB
    __shared__ float2 cnp[KCODES / 2];           // norms, k-pair packed

    {
        const float4* src = (const float4*)codebook;
        float4* dst = (float4*)cbs;
#pragma unroll
        for (int j = 0; j < 8; j++) dst[t + j * 128] = src[t + j * 128];
    }
    __syncthreads();

    // pack: cbp[p][i] = (cb[2p][i], cb[2p+1][i])
#pragma unroll
    for (int j = 0; j < 16; j++) {
        int q = t + j * 128;            // 0..2047
        int p = q >> 5, i = q & 31;
        cbp[p][i] = make_float2(cbs[(2 * p) * DDIM + i], cbs[(2 * p + 1) * DDIM + i]);
    }
    if (t < KCODES) {
        float s = 0.f;
#pragma unroll
        for (int i = 0; i < DDIM; i++) {
            float c = cbs[t * DDIM + i];
            s = fmaf(c, c, s);
        }
        ((float*)cnp)[t] = s;           // cnp[p] = (cn[2p], cn[2p+1])
    }
    __syncthreads();

    for (int chunk = bid - NSTORE; chunk < nChunks; chunk += NCOMP) {
        const long long n0 = (long long)chunk * 256 + t;  // vector 0
        const long long n1 = n0 + 128;                    // vector 1

        // load both vectors; duplicate each component into f32x2 pairs
        float2 xa[DDIM], xb[DDIM];
        {
            const float4* la = (const float4*)(latent + n0 * DDIM);
            const float4* lb = (const float4*)(latent + n1 * DDIM);
#pragma unroll
            for (int j = 0; j < 8; j++) {
                float4 v = __ldcs(&la[j]);
                xa[4 * j + 0] = make_float2(v.x, v.x);
                xa[4 * j + 1] = make_float2(v.y, v.y);
                xa[4 * j + 2] = make_float2(v.z, v.z);
                xa[4 * j + 3] = make_float2(v.w, v.w);
                float4 w = __ldcs(&lb[j]);
                xb[4 * j + 0] = make_float2(w.x, w.x);
                xb[4 * j + 1] = make_float2(w.y, w.y);
                xb[4 * j + 2] = make_float2(w.z, w.z);
                xb[4 * j + 3] = make_float2(w.w, w.w);
            }
        }

        // ||x||^2 — sequential fma chains (bit-match reference; DO NOT reorder)
        float xx0 = 0.f, xx1 = 0.f;
#pragma unroll
        for (int i = 0; i < DDIM; i++) xx0 = fmaf(xa[i].x, xa[i].x, xx0);
#pragma unroll
        for (int i = 0; i < DDIM; i++) xx1 = fmaf(xb[i].x, xb[i].x, xx1);

        // argmin: 64 k-pairs; one packed code row feeds both vectors' chains.
        float best0 = __int_as_float(0x7f800000);
        float best1 = __int_as_float(0x7f800000);
        int bk0 = 0, bk1 = 0;
#pragma unroll 1
        for (int p = 0; p < KCODES / 2; p++) {
            float2 dot0 = make_float2(0.f, 0.f);
            float2 dot1 = make_float2(0.f, 0.f);
            const float4* r = (const float4*)cbp[p];   // 16 x float4
#pragma unroll
            for (int j = 0; j < 16; j++) {
                float4 a = r[j];
                float2 cl = make_float2(a.x, a.y);     // i = 2j
                float2 ch = make_float2(a.z, a.w);     // i = 2j+1
                dot0 = ffma2(xa[2 * j],     cl, dot0);
                dot0 = ffma2(xa[2 * j + 1], ch, dot0);
                dot1 = ffma2(xb[2 * j],     cl, dot1);
                dot1 = ffma2(xb[2 * j + 1], ch, dot1);
            }
            float2 cn2 = cnp[p];
            float d00 = (xx0 + cn2.x) - 2.0f * dot0.x;
            float d01 = (xx0 + cn2.y) - 2.0f * dot0.y;
            float d10 = (xx1 + cn2.x) - 2.0f * dot1.x;
            float d11 = (xx1 + cn2.y) - 2.0f * dot1.y;
            if (d00 < best0) { best0 = d00; bk0 = 2 * p; }
            if (d01 < best0) { best0 = d01; bk0 = 2 * p + 1; }
            if (d10 < best1) { best1 = d10; bk1 = 2 * p; }
            if (d11 < best1) { best1 = d11; bk1 = 2 * p + 1; }
        }

        // epilogue: quantized + policy for both vectors
        {
            float4* qo = (float4*)(out_quant + n0 * DDIM);
            float4* po = (float4*)(out_policy + n0 * DDIM);
            const float4* cq = (const float4*)(cbs + bk0 * DDIM);
#pragma unroll
            for (int j = 0; j < 8; j++) {
                float4 q = cq[j];
                float4 p4;
                p4.x = xa[4 * j + 0].x + (q.x - xa[4 * j + 0].x);
                p4.y = xa[4 * j + 1].x + (q.y - xa[4 * j + 1].x);
                p4.z = xa[4 * j + 2].x + (q.z - xa[4 * j + 2].x);
                p4.w = xa[4 * j + 3].x + (q.w - xa[4 * j + 3].x);
                __stcs(&qo[j], q);
                __stcs(&po[j], p4);
            }
        }
        {
            float4* qo = (float4*)(out_quant + n1 * DDIM);
            float4* po = (float4*)(out_policy + n1 * DDIM);
            const float4* cq = (const float4*)(cbs + bk1 * DDIM);
#pragma unroll
            for (int j = 0; j < 8; j++) {
                float4 q = cq[j];
                float4 p4;
                p4.x = xb[4 * j + 0].x + (q.x - xb[4 * j + 0].x);
                p4.y = xb[4 * j + 1].x + (q.y - xb[4 * j + 1].x);
                p4.z = xb[4 * j + 2].x + (q.z - xb[4 * j + 2].x);
                p4.w = xb[4 * j + 3].x + (q.w - xb[4 * j + 3].x);
                __stcs(&qo[j], q);
                __stcs(&po[j], p4);
            }
        }
    }
}

extern "C" void kernel_launch(void* const* d_in, const int* in_sizes, int n_in,
                              void* d_out, int out_size) {
    const float* latent = (const float*)d_in[0];
    const float* codebook = (const float*)d_in[1];

    const long long Nvec = (long long)in_sizes[0] / DDIM;   // 262144
    const int nBatch = (int)(Nvec / 8);                     // 32768
    const int nChunks = (int)(Nvec / 256);                  // 1024

    float* out_policy = (float*)d_out;
    float* out_quant = out_policy + Nvec * DDIM;
    float* out_cbset = out_quant + Nvec * DDIM;

    vq_kernel<<<NGRID, 128>>>(latent, codebook, out_policy, out_quant,
                              out_cbset, nChunks, nBatch);
}